// round 8
// baseline (speedup 1.0000x reference)
#include <cuda_runtime.h>
#include <float.h>

#define NB   8192
#define NBAT 16
#define MS   1024
#define KNN  16
#define PPT  8        // FPS points per thread (8192 / 1024)
#define NPR  (PPT/2)  // packed pairs per thread
#define CH   2048     // KNN shared-memory chunk (points)
#define KW   8        // KNN warps per CTA (centroids per CTA)
#define FULLM 0xFFFFFFFFu

// ---- f32x2 helpers: two independent rn fp32 ops per instruction -----------
__device__ __forceinline__ unsigned long long f2pack(float lo, float hi) {
    unsigned long long d;
    asm("mov.b64 %0, {%1, %2};" : "=l"(d)
        : "r"(__float_as_uint(lo)), "r"(__float_as_uint(hi)));
    return d;
}
__device__ __forceinline__ void f2unpack(float& lo, float& hi, unsigned long long s) {
    unsigned a, b;
    asm("mov.b64 {%0, %1}, %2;" : "=r"(a), "=r"(b) : "l"(s));
    lo = __uint_as_float(a); hi = __uint_as_float(b);
}
__device__ __forceinline__ unsigned long long f2add(unsigned long long a,
                                                    unsigned long long b) {
    unsigned long long d;
    asm("add.rn.f32x2 %0, %1, %2;" : "=l"(d) : "l"(a), "l"(b));
    return d;
}
__device__ __forceinline__ unsigned long long f2mul(unsigned long long a,
                                                    unsigned long long b) {
    unsigned long long d;
    asm("mul.rn.f32x2 %0, %1, %2;" : "=l"(d) : "l"(a), "l"(b));
    return d;
}
__device__ __forceinline__ unsigned long long f2fma(unsigned long long a,
                                                    unsigned long long b,
                                                    unsigned long long c) {
    unsigned long long d;
    asm("fma.rn.f32x2 %0, %1, %2, %3;" : "=l"(d) : "l"(a), "l"(b), "l"(c));
    return d;
}

// ---------------------------------------------------------------------------
// Kernel 1: farthest point sampling. One CTA per batch, 1024 threads.
// Distance pass: packed f32x2 mul/add in the verified association
// ((dx*dx + dy*dy) + dz*dz) — bitwise identical per lane (no FMA contraction;
// subtract = add of exactly-negated q).
// Per-step argmax, ONE barrier, no atomics:
//   warp: redux.max(value bits)  [nonneg floats: u32-bit order == fp order]
//         per-thread lowest-k scan (SEL chain) -> encode ~globalidx
//         redux.max(~idx among value-winners)  -> warp (val, minidx)
//   lane0 stores u64 {val,~idx} slot (double-buffered by step parity)
//   __syncthreads
//   every warp: LDS.64 slots lane-indexed, redux.max val, redux.max masked
//   ~idx -> all threads compute cur identically. == jnp.argmax first-occ.
// ---------------------------------------------------------------------------
__global__ __launch_bounds__(1024, 1)
void fps_kernel(const float* __restrict__ pos, float* __restrict__ out_cent) {
    extern __shared__ float sh[];
    float* shx = sh;
    float* shy = sh + NB;
    float* shz = sh + 2 * NB;
    __shared__ unsigned long long shk[2][32];

    const int b    = blockIdx.x;
    const int tid  = threadIdx.x;
    const int lane = tid & 31;
    const int w    = tid >> 5;
    const float* pb = pos + (size_t)b * NB * 3;

    for (int i = tid; i < NB; i += 1024) {
        shx[i] = pb[3 * i + 0];
        shy[i] = pb[3 * i + 1];
        shz[i] = pb[3 * i + 2];
    }
    __syncthreads();

    // pair p holds global indices tid + 2p*1024 (lo) and tid + (2p+1)*1024 (hi)
    unsigned long long rx2[NPR], ry2[NPR], rz2[NPR];
    float md[PPT];
#pragma unroll
    for (int p = 0; p < NPR; p++) {
        int i0 = tid + ((2 * p) << 10);
        int i1 = i0 + 1024;
        rx2[p] = f2pack(shx[i0], shx[i1]);
        ry2[p] = f2pack(shy[i0], shy[i1]);
        rz2[p] = f2pack(shz[i0], shz[i1]);
        md[2 * p] = FLT_MAX; md[2 * p + 1] = FLT_MAX;
    }

    int cur = 0;
    for (int s = 0;; s++) {
        float qx = shx[cur], qy = shy[cur], qz = shz[cur];
        if (tid == 0) {
            float* oc = out_cent + ((size_t)b * MS + s) * 3;
            oc[0] = qx; oc[1] = qy; oc[2] = qz;
        }
        if (s == MS - 1) break;

        unsigned long long nqx = f2pack(-qx, -qx);
        unsigned long long nqy = f2pack(-qy, -qy);
        unsigned long long nqz = f2pack(-qz, -qz);

#pragma unroll
        for (int p = 0; p < NPR; p++) {
            unsigned long long dx = f2add(rx2[p], nqx);
            unsigned long long dy = f2add(ry2[p], nqy);
            unsigned long long dz = f2add(rz2[p], nqz);
            unsigned long long sx = f2mul(dx, dx);
            unsigned long long sy = f2mul(dy, dy);
            unsigned long long sz = f2mul(dz, dz);
            unsigned long long d2 = f2add(f2add(sx, sy), sz);  // ((x²+y²)+z²)
            float a, c;
            f2unpack(a, c, d2);
            md[2 * p]     = fminf(md[2 * p],     a);
            md[2 * p + 1] = fminf(md[2 * p + 1], c);
        }

        // per-thread max as 7-op tree (fmax exactly order-independent)
        float t01 = fmaxf(md[0], md[1]), t23 = fmaxf(md[2], md[3]);
        float t45 = fmaxf(md[4], md[5]), t67 = fmaxf(md[6], md[7]);
        float t03 = fmaxf(t01, t23),     t47 = fmaxf(t45, t67);
        float tmax = fmaxf(t03, t47);

        // warp reduce: value (bit-monotone for nonneg floats), then min index
        const unsigned tb = __float_as_uint(tmax);
        const unsigned wv = __reduce_max_sync(FULLM, tb);
        int kmin = 0;
#pragma unroll
        for (int kk = PPT - 1; kk >= 0; kk--)   // descending -> lowest k wins
            if (md[kk] == tmax) kmin = kk;
        const unsigned enc = (tb == wv)
            ? (0xFFFFFFFFu - (unsigned)(tid + (kmin << 10))) : 0u;
        const unsigned wi = __reduce_max_sync(FULLM, enc);
        if (lane == 0)
            shk[s & 1][w] = ((unsigned long long)wv << 32) | wi;
        __syncthreads();                                   // the only barrier

        const unsigned long long slot = shk[s & 1][lane];
        const unsigned v = (unsigned)(slot >> 32);
        const unsigned g = __reduce_max_sync(FULLM, v);
        const unsigned ci = (v == g) ? (unsigned)slot : 0u;
        const unsigned gi = __reduce_max_sync(FULLM, ci);
        cur = (int)(0xFFFFFFFFu - gi);
    }
}

// ---------------------------------------------------------------------------
// Kernel 2: 16-NN + gather. One WARP per centroid, 8 warps/CTA, 2048 CTAs.
// 2 points/lane via packed f32x2 from SoA smem (aligned LDS.64, immediate
// offsets from one hoisted base). d2 pipeline bitwise-matches the reference:
//   csum/psum: rn mul/add chain; dot: fma(cz,pz, fma(cy,py, cx*px));
//   d2 = fma(-2, dot, csum) + psum   [2*dot is exact (power-of-2 scale), so
//   this fma rounds only the sum — identical to (csum - 2*dot)] then + psum.
// Fast path: 5 packed fp ops + OR-combined setp + ONE ballot per 64 points.
// Top-16 distributed in lanes 0..15, sorted by lexicographic (d2, idx);
// exact lex gate vs entry 15 makes the kept set the 16 lex-smallest keys
// independent of arrival order == lax.top_k stable result.
// ---------------------------------------------------------------------------
__global__ __launch_bounds__(256)
void knn_kernel(const float* __restrict__ pos, const float* __restrict__ cent,
                float* __restrict__ out_grp) {
    __shared__ alignas(16) float sxx[CH];
    __shared__ alignas(16) float syy[CH];
    __shared__ alignas(16) float szz[CH];
    __shared__ alignas(16) float sww[CH];
    const int lane = threadIdx.x & 31;
    const int wid  = threadIdx.x >> 5;
    const int b    = blockIdx.x >> 7;                    // 128 CTAs per batch
    const int m    = ((blockIdx.x & 127) * KW) + wid;    // centroid in batch

    const float* cp = cent + ((size_t)b * MS + m) * 3;
    const float cx = cp[0], cy = cp[1], cz = cp[2];
    const float csum = __fadd_rn(__fadd_rn(__fmul_rn(cx, cx), __fmul_rn(cy, cy)),
                                 __fmul_rn(cz, cz));
    const unsigned long long cx2 = f2pack(cx, cx);
    const unsigned long long cy2 = f2pack(cy, cy);
    const unsigned long long cz2 = f2pack(cz, cz);
    const unsigned long long cs2 = f2pack(csum, csum);
    const unsigned long long n2  = f2pack(-2.0f, -2.0f);
    const float* pb = pos + (size_t)b * NB * 3;

    float bd = FLT_MAX;          // lane's list entry (lanes 0..15 meaningful)
    int   bi = 0x7FFFFFFF;
    float th_d = FLT_MAX;        // entry 15 (d2, idx)
    int   th_i = 0x7FFFFFFF;

    // warp-parallel sorted insert; gate + list maintained under lex (d2,idx).
    // All branches warp-uniform (cd/ci/th broadcast) -> syncs inside are safe.
    auto try_insert = [&](float cd, int ci) {
        if ((cd < th_d) || (cd == th_d && ci < th_i)) {
            const bool less = (bd < cd) || (bd == cd && bi < ci);
            const unsigned lm = __ballot_sync(FULLM, less) & 0xFFFFu;
            const int pp = __popc(lm);
            const float ud = __shfl_up_sync(FULLM, bd, 1);
            const int   ui = __shfl_up_sync(FULLM, bi, 1);
            if (lane == pp)      { bd = cd; bi = ci; }
            else if (lane > pp)  { bd = ud; bi = ui; }
            th_d = __shfl_sync(FULLM, bd, 15);
            th_i = __shfl_sync(FULLM, bi, 15);
        }
    };

    const int lo2 = 2 * lane;    // hoisted pair base within a 64-pt group

    for (int c0 = 0; c0 < NB; c0 += CH) {
        __syncthreads();
        for (int j = threadIdx.x; j < CH; j += 256) {
            float px = pb[3 * (c0 + j) + 0];
            float py = pb[3 * (c0 + j) + 1];
            float pz = pb[3 * (c0 + j) + 2];
            float ps = __fadd_rn(__fadd_rn(__fmul_rn(px, px), __fmul_rn(py, py)),
                                 __fmul_rn(pz, pz));
            sxx[j] = px; syy[j] = py; szz[j] = pz; sww[j] = ps;
        }
        __syncthreads();

#pragma unroll 4
        for (int jj = 0; jj < CH; jj += 64) {
            const int o = jj + lo2;
            const unsigned long long px2 =
                *reinterpret_cast<const unsigned long long*>(sxx + o);
            const unsigned long long py2 =
                *reinterpret_cast<const unsigned long long*>(syy + o);
            const unsigned long long pz2 =
                *reinterpret_cast<const unsigned long long*>(szz + o);
            const unsigned long long pw2 =
                *reinterpret_cast<const unsigned long long*>(sww + o);

            const unsigned long long dot2 =
                f2fma(cz2, pz2, f2fma(cy2, py2, f2mul(cx2, px2)));
            // fma(-2, dot, csum): exact product -> rounds identically to
            // (csum - 2*dot); then + psum.
            const unsigned long long d2p =
                f2add(f2fma(n2, dot2, cs2), pw2);
            float d2a, d2b;
            f2unpack(d2a, d2b, d2p);               // points o, o+1

            const unsigned mhit =
                __ballot_sync(FULLM, (d2a <= th_d) | (d2b <= th_d));
            if (mhit) {
                unsigned mk = mhit;
                do {                               // rare slow path
                    const int src = __ffs(mk) - 1;
                    mk &= mk - 1;
                    const float ca = __shfl_sync(FULLM, d2a, src);
                    const float cb = __shfl_sync(FULLM, d2b, src);
                    const int base = c0 + jj + 2 * src;
                    try_insert(ca, base);
                    try_insert(cb, base + 1);
                } while (mk);
            }
        }
    }

    if (lane < KNN) {
        const int i = bi;
        float* og = out_grp + ((size_t)((size_t)b * MS + m) * KNN + lane) * 3;
        og[0] = pb[3 * i + 0];
        og[1] = pb[3 * i + 1];
        og[2] = pb[3 * i + 2];
    }
}

// ---------------------------------------------------------------------------
// kernel_launch: d_in = [x (unused), pos, batch]; out = [centroids | groups].
// Graph-capturable: two kernel launches, no allocs, no syncs.
// ---------------------------------------------------------------------------
extern "C" void kernel_launch(void* const* d_in, const int* in_sizes, int n_in,
                              void* d_out, int out_size) {
    (void)in_sizes; (void)n_in; (void)out_size;
    const float* pos = (const float*)d_in[1];
    float* out      = (float*)d_out;
    float* out_cent = out;                              // B*M*3   = 49152
    float* out_grp  = out + (size_t)NBAT * MS * 3;      // B*M*K*3 = 786432

    const size_t fps_smem = (size_t)3 * NB * sizeof(float);
    cudaFuncSetAttribute(fps_kernel, cudaFuncAttributeMaxDynamicSharedMemorySize,
                         (int)fps_smem);

    fps_kernel<<<NBAT, 1024, fps_smem>>>(pos, out_cent);
    knn_kernel<<<NBAT * (MS / KW), 256>>>(pos, out_cent, out_grp);
}

// round 10
// speedup vs baseline: 1.1434x; 1.1434x over previous
#include <cuda_runtime.h>
#include <float.h>

#define NB   8192
#define NBAT 16
#define MS   1024
#define KNN  16
#define PPT  8        // FPS points per thread (8192 / 1024)
#define NPR  (PPT/2)  // packed pairs per thread
#define CH   2048     // KNN shared-memory chunk (points)
#define FULLM 0xFFFFFFFFu

// ---- f32x2 helpers: two independent rn fp32 ops per instruction -----------
__device__ __forceinline__ unsigned long long f2pack(float lo, float hi) {
    unsigned long long d;
    asm("mov.b64 %0, {%1, %2};" : "=l"(d)
        : "r"(__float_as_uint(lo)), "r"(__float_as_uint(hi)));
    return d;
}
__device__ __forceinline__ void f2unpack(float& lo, float& hi, unsigned long long s) {
    unsigned a, b;
    asm("mov.b64 {%0, %1}, %2;" : "=r"(a), "=r"(b) : "l"(s));
    lo = __uint_as_float(a); hi = __uint_as_float(b);
}
__device__ __forceinline__ unsigned long long f2add(unsigned long long a,
                                                    unsigned long long b) {
    unsigned long long d;
    asm("add.rn.f32x2 %0, %1, %2;" : "=l"(d) : "l"(a), "l"(b));
    return d;
}
__device__ __forceinline__ unsigned long long f2mul(unsigned long long a,
                                                    unsigned long long b) {
    unsigned long long d;
    asm("mul.rn.f32x2 %0, %1, %2;" : "=l"(d) : "l"(a), "l"(b));
    return d;
}
__device__ __forceinline__ unsigned long long f2fma(unsigned long long a,
                                                    unsigned long long b,
                                                    unsigned long long c) {
    unsigned long long d;
    asm("fma.rn.f32x2 %0, %1, %2, %3;" : "=l"(d) : "l"(a), "l"(b), "l"(c));
    return d;
}

// ---------------------------------------------------------------------------
// Kernel 1: farthest point sampling — ROUND-7 reduction (measured 475us),
// reverted after the round-8 one-barrier rework regressed (+160 cyc/step of
// serialized redux latency). Per step:
//   redux.max warp value -> 32 smem slots -> bar1 -> every warp redux over
//   slots -> threads holding the max scan md (conditional) + atomicMin of
//   global index (1-2 participants) -> bar2. Double-buffered index slot.
// Distance pass: packed f32x2 in the verified association ((dx²+dy²)+dz²),
// bitwise identical per lane. Semantics == jnp.argmax first occurrence.
// ---------------------------------------------------------------------------
__global__ __launch_bounds__(1024, 1)
void fps_kernel(const float* __restrict__ pos, float* __restrict__ out_cent) {
    extern __shared__ float sh[];
    float* shx = sh;
    float* shy = sh + NB;
    float* shz = sh + 2 * NB;
    __shared__ unsigned shw[32];
    __shared__ int shidx2[2];

    const int b    = blockIdx.x;
    const int tid  = threadIdx.x;
    const int lane = tid & 31;
    const int w    = tid >> 5;
    const float* pb = pos + (size_t)b * NB * 3;

    for (int i = tid; i < NB; i += 1024) {
        shx[i] = pb[3 * i + 0];
        shy[i] = pb[3 * i + 1];
        shz[i] = pb[3 * i + 2];
    }
    if (tid == 0) { shidx2[0] = 0x7FFFFFFF; shidx2[1] = 0x7FFFFFFF; }
    __syncthreads();

    // pair p holds global indices tid + 2p*1024 (lo) and tid + (2p+1)*1024 (hi)
    unsigned long long rx2[NPR], ry2[NPR], rz2[NPR];
    float md[PPT];
#pragma unroll
    for (int p = 0; p < NPR; p++) {
        int i0 = tid + ((2 * p) << 10);
        int i1 = i0 + 1024;
        rx2[p] = f2pack(shx[i0], shx[i1]);
        ry2[p] = f2pack(shy[i0], shy[i1]);
        rz2[p] = f2pack(shz[i0], shz[i1]);
        md[2 * p] = FLT_MAX; md[2 * p + 1] = FLT_MAX;
    }

    int cur = 0;
    for (int s = 0;; s++) {
        float qx = shx[cur], qy = shy[cur], qz = shz[cur];
        if (tid == 0) {
            float* oc = out_cent + ((size_t)b * MS + s) * 3;
            oc[0] = qx; oc[1] = qy; oc[2] = qz;
        }
        if (s == MS - 1) break;

        unsigned long long nqx = f2pack(-qx, -qx);
        unsigned long long nqy = f2pack(-qy, -qy);
        unsigned long long nqz = f2pack(-qz, -qz);

#pragma unroll
        for (int p = 0; p < NPR; p++) {
            unsigned long long dx = f2add(rx2[p], nqx);
            unsigned long long dy = f2add(ry2[p], nqy);
            unsigned long long dz = f2add(rz2[p], nqz);
            unsigned long long sx = f2mul(dx, dx);
            unsigned long long sy = f2mul(dy, dy);
            unsigned long long sz = f2mul(dz, dz);
            unsigned long long d2 = f2add(f2add(sx, sy), sz);  // ((x²+y²)+z²)
            float a, c;
            f2unpack(a, c, d2);
            md[2 * p]     = fminf(md[2 * p],     a);
            md[2 * p + 1] = fminf(md[2 * p + 1], c);
        }

        // per-thread max as 7-op tree (fmax exactly order-independent)
        float t01 = fmaxf(md[0], md[1]), t23 = fmaxf(md[2], md[3]);
        float t45 = fmaxf(md[4], md[5]), t67 = fmaxf(md[6], md[7]);
        float tmax = fmaxf(fmaxf(t01, t23), fmaxf(t45, t67));

        // non-negative floats: bit pattern is order-preserving as u32
        const unsigned tb = __float_as_uint(tmax);
        const unsigned wv = __reduce_max_sync(FULLM, tb);
        if (lane == 0) shw[w] = wv;
        __syncthreads();                                   // barrier 1
        const unsigned g = __reduce_max_sync(FULLM, shw[lane]);
        if (tid == 0) shidx2[(s + 1) & 1] = 0x7FFFFFFF;    // reset next slot
        if (tb == g) {                                     // rare path
            const float gf = __uint_as_float(g);
            int k = 0;
#pragma unroll
            for (int kk = PPT - 1; kk >= 0; kk--)  // descending -> lowest k wins
                if (md[kk] == gf) k = kk;
            atomicMin(&shidx2[s & 1], tid + (k << 10));
        }
        __syncthreads();                                   // barrier 2
        cur = shidx2[s & 1];
    }
}

// ---------------------------------------------------------------------------
// Kernel 2: 16-NN + gather. TWO centroids per warp: list A in lanes 0..15,
// list B in lanes 16..31 (each sorted by lexicographic (d2, idx)). 8 warps /
// CTA -> 16 centroids per CTA, 1024 CTAs. The 4 LDS.64 per 64-pt group are
// amortized over both centroids; one combined ballot gates the slow path.
// d2 pipeline bitwise-matches the reference (round-8 verified):
//   csum/psum rn chains; dot = fma(cz,pz, fma(cy,py, cx*px));
//   d2 = fma(-2,dot,csum) + psum  [exact: -2*dot is a sign-flipped exact
//   power-of-2 product, so only the sum rounds — identical to csum-2*dot].
// Insert: position = 16*half + popc(less-ballot masked to the half); commits
// predicated on (lane>>4)==half; shfl_up lane-16 boundary is dead because
// the lex gate bounds pp within the half. Kept set per list = 16 lex-
// smallest (d2, idx) keys independent of order == lax.top_k stable result.
// ---------------------------------------------------------------------------
__global__ __launch_bounds__(256)
void knn_kernel(const float* __restrict__ pos, const float* __restrict__ cent,
                float* __restrict__ out_grp) {
    __shared__ alignas(16) float sxx[CH];
    __shared__ alignas(16) float syy[CH];
    __shared__ alignas(16) float szz[CH];
    __shared__ alignas(16) float sww[CH];
    const int lane = threadIdx.x & 31;
    const int wid  = threadIdx.x >> 5;
    const int b    = blockIdx.x >> 6;                    // 64 CTAs per batch
    const int m0   = ((blockIdx.x & 63) << 4) + wid * 2; // centroid pair base

    const float* cpA = cent + ((size_t)b * MS + m0) * 3;
    const float cxA = cpA[0], cyA = cpA[1], czA = cpA[2];
    const float cxB = cpA[3], cyB = cpA[4], czB = cpA[5];
    const float csA = __fadd_rn(__fadd_rn(__fmul_rn(cxA, cxA), __fmul_rn(cyA, cyA)),
                                __fmul_rn(czA, czA));
    const float csB = __fadd_rn(__fadd_rn(__fmul_rn(cxB, cxB), __fmul_rn(cyB, cyB)),
                                __fmul_rn(czB, czB));
    const unsigned long long cxA2 = f2pack(cxA, cxA), cxB2 = f2pack(cxB, cxB);
    const unsigned long long cyA2 = f2pack(cyA, cyA), cyB2 = f2pack(cyB, cyB);
    const unsigned long long czA2 = f2pack(czA, czA), czB2 = f2pack(czB, czB);
    const unsigned long long csA2 = f2pack(csA, csA), csB2 = f2pack(csB, csB);
    const unsigned long long n2   = f2pack(-2.0f, -2.0f);
    const float* pb = pos + (size_t)b * NB * 3;

    float bd = FLT_MAX;              // this lane's list entry
    int   bi = 0x7FFFFFFF;
    float thA_d = FLT_MAX, thB_d = FLT_MAX;   // entry-15 keys per list
    int   thA_i = 0x7FFFFFFF, thB_i = 0x7FFFFFFF;

    // warp-parallel sorted insert into half-warp list `half` (0=A,1=B).
    // All control warp-uniform (cd/ci broadcast, th uniform) -> syncs safe.
    auto try_insert = [&](float cd, int ci, int half, float& th_d, int& th_i) {
        if ((cd < th_d) || (cd == th_d && ci < th_i)) {
            const bool less = (bd < cd) || (bd == cd && bi < ci);
            const unsigned lm =
                (__ballot_sync(FULLM, less) >> (half << 4)) & 0xFFFFu;
            const int pp = (half << 4) + __popc(lm);
            const float ud = __shfl_up_sync(FULLM, bd, 1);
            const int   ui = __shfl_up_sync(FULLM, bi, 1);
            if ((lane >> 4) == half) {
                if (lane == pp)      { bd = cd; bi = ci; }
                else if (lane > pp)  { bd = ud; bi = ui; }
            }
            th_d = __shfl_sync(FULLM, bd, (half << 4) + 15);
            th_i = __shfl_sync(FULLM, bi, (half << 4) + 15);
        }
    };

    const int lo2 = 2 * lane;

    for (int c0 = 0; c0 < NB; c0 += CH) {
        __syncthreads();
        for (int j = threadIdx.x; j < CH; j += 256) {
            float px = pb[3 * (c0 + j) + 0];
            float py = pb[3 * (c0 + j) + 1];
            float pz = pb[3 * (c0 + j) + 2];
            float ps = __fadd_rn(__fadd_rn(__fmul_rn(px, px), __fmul_rn(py, py)),
                                 __fmul_rn(pz, pz));
            sxx[j] = px; syy[j] = py; szz[j] = pz; sww[j] = ps;
        }
        __syncthreads();

#pragma unroll 4
        for (int jj = 0; jj < CH; jj += 64) {
            const int o = jj + lo2;
            const unsigned long long px2 =
                *reinterpret_cast<const unsigned long long*>(sxx + o);
            const unsigned long long py2 =
                *reinterpret_cast<const unsigned long long*>(syy + o);
            const unsigned long long pz2 =
                *reinterpret_cast<const unsigned long long*>(szz + o);
            const unsigned long long pw2 =
                *reinterpret_cast<const unsigned long long*>(sww + o);

            const unsigned long long dotA =
                f2fma(czA2, pz2, f2fma(cyA2, py2, f2mul(cxA2, px2)));
            const unsigned long long dotB =
                f2fma(czB2, pz2, f2fma(cyB2, py2, f2mul(cxB2, px2)));
            const unsigned long long d2A =
                f2add(f2fma(n2, dotA, csA2), pw2);
            const unsigned long long d2B =
                f2add(f2fma(n2, dotB, csB2), pw2);
            float dAa, dAb, dBa, dBb;
            f2unpack(dAa, dAb, d2A);           // pts o, o+1 vs centroid A
            f2unpack(dBa, dBb, d2B);           // pts o, o+1 vs centroid B

            const bool hit = (dAa <= thA_d) | (dAb <= thA_d) |
                             (dBa <= thB_d) | (dBb <= thB_d);
            if (__ballot_sync(FULLM, hit)) {   // rare slow path
                const int base = c0 + jj;
                unsigned mk;
                mk = __ballot_sync(FULLM, dAa <= thA_d);
                while (mk) {
                    const int src = __ffs(mk) - 1; mk &= mk - 1;
                    try_insert(__shfl_sync(FULLM, dAa, src),
                               base + 2 * src, 0, thA_d, thA_i);
                }
                mk = __ballot_sync(FULLM, dAb <= thA_d);
                while (mk) {
                    const int src = __ffs(mk) - 1; mk &= mk - 1;
                    try_insert(__shfl_sync(FULLM, dAb, src),
                               base + 2 * src + 1, 0, thA_d, thA_i);
                }
                mk = __ballot_sync(FULLM, dBa <= thB_d);
                while (mk) {
                    const int src = __ffs(mk) - 1; mk &= mk - 1;
                    try_insert(__shfl_sync(FULLM, dBa, src),
                               base + 2 * src, 1, thB_d, thB_i);
                }
                mk = __ballot_sync(FULLM, dBb <= thB_d);
                while (mk) {
                    const int src = __ffs(mk) - 1; mk &= mk - 1;
                    try_insert(__shfl_sync(FULLM, dBb, src),
                               base + 2 * src + 1, 1, thB_d, thB_i);
                }
            }
        }
    }

    // lanes 0..15 -> centroid m0, lanes 16..31 -> centroid m0+1
    {
        const int mm = m0 + (lane >> 4);
        const int kk = lane & 15;
        const int i  = bi;
        float* og = out_grp + ((size_t)((size_t)b * MS + mm) * KNN + kk) * 3;
        og[0] = pb[3 * i + 0];
        og[1] = pb[3 * i + 1];
        og[2] = pb[3 * i + 2];
    }
}

// ---------------------------------------------------------------------------
// kernel_launch: d_in = [x (unused), pos, batch]; out = [centroids | groups].
// Graph-capturable: two kernel launches, no allocs, no syncs.
// ---------------------------------------------------------------------------
extern "C" void kernel_launch(void* const* d_in, const int* in_sizes, int n_in,
                              void* d_out, int out_size) {
    (void)in_sizes; (void)n_in; (void)out_size;
    const float* pos = (const float*)d_in[1];
    float* out      = (float*)d_out;
    float* out_cent = out;                              // B*M*3   = 49152
    float* out_grp  = out + (size_t)NBAT * MS * 3;      // B*M*K*3 = 786432

    const size_t fps_smem = (size_t)3 * NB * sizeof(float);
    cudaFuncSetAttribute(fps_kernel, cudaFuncAttributeMaxDynamicSharedMemorySize,
                         (int)fps_smem);

    fps_kernel<<<NBAT, 1024, fps_smem>>>(pos, out_cent);
    knn_kernel<<<NBAT * (MS / 16), 256>>>(pos, out_cent, out_grp);
}

// round 15
// speedup vs baseline: 1.2174x; 1.0647x over previous
#include <cuda_runtime.h>
#include <float.h>

#define NB   8192
#define NBAT 16
#define MS   1024
#define KNN  16
#define PPT  8        // FPS points per thread (8192 / 1024)
#define NPR  (PPT/2)  // packed pairs per thread
#define CH   2048     // KNN shared-memory chunk (points)
#define GRP  64       // centroids per work item
#define NITEM (NBAT * (MS / GRP))   // 256 work items
#define NWORK 148     // total CTAs (16 FPS + 132 pure workers)
#define FULLM 0xFFFFFFFFu

// ---- work queue / progress (device globals — no allocation) ---------------
__device__ int g_queue;
__device__ int g_progress[NBAT];

// ---- f32x2 helpers: two independent rn fp32 ops per instruction -----------
__device__ __forceinline__ unsigned long long f2pack(float lo, float hi) {
    unsigned long long d;
    asm("mov.b64 %0, {%1, %2};" : "=l"(d)
        : "r"(__float_as_uint(lo)), "r"(__float_as_uint(hi)));
    return d;
}
__device__ __forceinline__ void f2unpack(float& lo, float& hi, unsigned long long s) {
    unsigned a, b;
    asm("mov.b64 {%0, %1}, %2;" : "=r"(a), "=r"(b) : "l"(s));
    lo = __uint_as_float(a); hi = __uint_as_float(b);
}
__device__ __forceinline__ unsigned long long f2add(unsigned long long a,
                                                    unsigned long long b) {
    unsigned long long d;
    asm("add.rn.f32x2 %0, %1, %2;" : "=l"(d) : "l"(a), "l"(b));
    return d;
}
__device__ __forceinline__ unsigned long long f2mul(unsigned long long a,
                                                    unsigned long long b) {
    unsigned long long d;
    asm("mul.rn.f32x2 %0, %1, %2;" : "=l"(d) : "l"(a), "l"(b));
    return d;
}
__device__ __forceinline__ unsigned long long f2fma(unsigned long long a,
                                                    unsigned long long b,
                                                    unsigned long long c) {
    unsigned long long d;
    asm("fma.rn.f32x2 %0, %1, %2, %3;" : "=l"(d) : "l"(a), "l"(b), "l"(c));
    return d;
}

// ---------------------------------------------------------------------------
// init kernel: reset queue + per-batch progress. Runs before the fused kernel
// on the same stream each graph replay (graph edge orders the stores).
// ---------------------------------------------------------------------------
__global__ void init_kernel() {
    if (threadIdx.x == 0) g_queue = 0;
    if (threadIdx.x < NBAT) g_progress[threadIdx.x] = 0;
}

// ---------------------------------------------------------------------------
// Fused persistent kernel. 148 CTAs x 1024 threads, 132KB dynamic smem
// (1 CTA/SM: workers never share an SM with an FPS CTA; all CTAs resident).
//   CTA 0..15   : FPS for batch b (round-10 verified bitwise-exact path);
//                 publishes progress every 64 centroids via
//                 __threadfence + atomicExch (release); then joins the queue.
//   CTA 16..147 : KNN workers. Item = (batch, 64-centroid group); tid0 polls
//                 progress via atomicAdd(p,0) (L2-coherent) + __threadfence
//                 (acquire), then the round-10 KNN body (2 centroids/warp).
// Termination is scheduling-independent: FPS CTAs never wait; progress is
// monotone; any scheduled worker finishes and frees its SM.
// All numerics byte-identical to the round-10 kernels (rel_err == 0).
// ---------------------------------------------------------------------------
__global__ __launch_bounds__(1024, 1)
void fused_kernel(const float* __restrict__ pos, float* out_cent,
                  float* out_grp) {
    extern __shared__ float sh[];
    __shared__ unsigned shw[32];
    __shared__ int shidx2[2];
    __shared__ int s_item;

    const int tid  = threadIdx.x;
    const int lane = tid & 31;
    const int w    = tid >> 5;

    // ======================= FPS phase (CTAs 0..15) ========================
    if (blockIdx.x < NBAT) {
        float* shx = sh;
        float* shy = sh + NB;
        float* shz = sh + 2 * NB;
        const int b = blockIdx.x;
        const float* pb = pos + (size_t)b * NB * 3;

        for (int i = tid; i < NB; i += 1024) {
            shx[i] = pb[3 * i + 0];
            shy[i] = pb[3 * i + 1];
            shz[i] = pb[3 * i + 2];
        }
        if (tid == 0) { shidx2[0] = 0x7FFFFFFF; shidx2[1] = 0x7FFFFFFF; }
        __syncthreads();

        unsigned long long rx2[NPR], ry2[NPR], rz2[NPR];
        float md[PPT];
#pragma unroll
        for (int p = 0; p < NPR; p++) {
            int i0 = tid + ((2 * p) << 10);
            int i1 = i0 + 1024;
            rx2[p] = f2pack(shx[i0], shx[i1]);
            ry2[p] = f2pack(shy[i0], shy[i1]);
            rz2[p] = f2pack(shz[i0], shz[i1]);
            md[2 * p] = FLT_MAX; md[2 * p + 1] = FLT_MAX;
        }

        int cur = 0;
        for (int s = 0;; s++) {
            float qx = shx[cur], qy = shy[cur], qz = shz[cur];
            if (tid == 0) {
                float* oc = out_cent + ((size_t)b * MS + s) * 3;
                oc[0] = qx; oc[1] = qy; oc[2] = qz;
                if (((s + 1) & (GRP - 1)) == 0) {        // release 64-group
                    __threadfence();                     // order prior stores
                    atomicExch(&g_progress[b], s + 1);   // L2-visible publish
                }
            }
            if (s == MS - 1) break;

            unsigned long long nqx = f2pack(-qx, -qx);
            unsigned long long nqy = f2pack(-qy, -qy);
            unsigned long long nqz = f2pack(-qz, -qz);

#pragma unroll
            for (int p = 0; p < NPR; p++) {
                unsigned long long dx = f2add(rx2[p], nqx);
                unsigned long long dy = f2add(ry2[p], nqy);
                unsigned long long dz = f2add(rz2[p], nqz);
                unsigned long long sx = f2mul(dx, dx);
                unsigned long long sy = f2mul(dy, dy);
                unsigned long long sz = f2mul(dz, dz);
                unsigned long long d2 = f2add(f2add(sx, sy), sz);
                float a, c;
                f2unpack(a, c, d2);
                md[2 * p]     = fminf(md[2 * p],     a);
                md[2 * p + 1] = fminf(md[2 * p + 1], c);
            }

            float t01 = fmaxf(md[0], md[1]), t23 = fmaxf(md[2], md[3]);
            float t45 = fmaxf(md[4], md[5]), t67 = fmaxf(md[6], md[7]);
            float tmax = fmaxf(fmaxf(t01, t23), fmaxf(t45, t67));

            const unsigned tb = __float_as_uint(tmax);
            const unsigned wv = __reduce_max_sync(FULLM, tb);
            if (lane == 0) shw[w] = wv;
            __syncthreads();                               // barrier 1
            const unsigned g = __reduce_max_sync(FULLM, shw[lane]);
            if (tid == 0) shidx2[(s + 1) & 1] = 0x7FFFFFFF;
            if (tb == g) {                                 // rare path
                const float gf = __uint_as_float(g);
                int k = 0;
#pragma unroll
                for (int kk = PPT - 1; kk >= 0; kk--)
                    if (md[kk] == gf) k = kk;
                atomicMin(&shidx2[s & 1], tid + (k << 10));
            }
            __syncthreads();                               // barrier 2
            cur = shidx2[s & 1];
        }
    }

    // ===================== KNN worker phase (all CTAs) =====================
    float* sxx = sh;
    float* syy = sh + CH;
    float* szz = sh + 2 * CH;
    float* sww = sh + 3 * CH;
    const int wid = w;                    // 0..31

    for (;;) {
        __syncthreads();                  // protect s_item + smem reuse
        if (tid == 0) s_item = atomicAdd(&g_queue, 1);
        __syncthreads();
        const int item = s_item;
        if (item >= NITEM) break;
        const int b  = item >> 4;         // 16 groups per batch
        const int gg = item & 15;
        const int need = (gg + 1) * GRP;

        if (tid == 0) {
            while (atomicAdd(&g_progress[b], 0) < need)    // L2-coherent poll
                __nanosleep(1024);
            __threadfence();                               // acquire
        }
        __syncthreads();

        const int m0 = (gg << 6) + wid * 2;     // centroid pair for this warp
        const float* cpA = out_cent + ((size_t)b * MS + m0) * 3;
        const float cxA = cpA[0], cyA = cpA[1], czA = cpA[2];
        const float cxB = cpA[3], cyB = cpA[4], czB = cpA[5];
        const float csA = __fadd_rn(__fadd_rn(__fmul_rn(cxA, cxA),
                                              __fmul_rn(cyA, cyA)),
                                    __fmul_rn(czA, czA));
        const float csB = __fadd_rn(__fadd_rn(__fmul_rn(cxB, cxB),
                                              __fmul_rn(cyB, cyB)),
                                    __fmul_rn(czB, czB));
        const unsigned long long cxA2 = f2pack(cxA, cxA), cxB2 = f2pack(cxB, cxB);
        const unsigned long long cyA2 = f2pack(cyA, cyA), cyB2 = f2pack(cyB, cyB);
        const unsigned long long czA2 = f2pack(czA, czA), czB2 = f2pack(czB, czB);
        const unsigned long long csA2 = f2pack(csA, csA), csB2 = f2pack(csB, csB);
        const unsigned long long n2   = f2pack(-2.0f, -2.0f);
        const float* pb = pos + (size_t)b * NB * 3;

        float bd = FLT_MAX;
        int   bi = 0x7FFFFFFF;
        float thA_d = FLT_MAX, thB_d = FLT_MAX;
        int   thA_i = 0x7FFFFFFF, thB_i = 0x7FFFFFFF;

        auto try_insert = [&](float cd, int ci, int half, float& th_d, int& th_i) {
            if ((cd < th_d) || (cd == th_d && ci < th_i)) {
                const bool less = (bd < cd) || (bd == cd && bi < ci);
                const unsigned lm =
                    (__ballot_sync(FULLM, less) >> (half << 4)) & 0xFFFFu;
                const int pp = (half << 4) + __popc(lm);
                const float ud = __shfl_up_sync(FULLM, bd, 1);
                const int   ui = __shfl_up_sync(FULLM, bi, 1);
                if ((lane >> 4) == half) {
                    if (lane == pp)      { bd = cd; bi = ci; }
                    else if (lane > pp)  { bd = ud; bi = ui; }
                }
                th_d = __shfl_sync(FULLM, bd, (half << 4) + 15);
                th_i = __shfl_sync(FULLM, bi, (half << 4) + 15);
            }
        };

        const int lo2 = 2 * lane;

        for (int c0 = 0; c0 < NB; c0 += CH) {
            __syncthreads();
            for (int j = tid; j < CH; j += 1024) {
                float px = pb[3 * (c0 + j) + 0];
                float py = pb[3 * (c0 + j) + 1];
                float pz = pb[3 * (c0 + j) + 2];
                float ps = __fadd_rn(__fadd_rn(__fmul_rn(px, px),
                                               __fmul_rn(py, py)),
                                     __fmul_rn(pz, pz));
                sxx[j] = px; syy[j] = py; szz[j] = pz; sww[j] = ps;
            }
            __syncthreads();

#pragma unroll 4
            for (int jj = 0; jj < CH; jj += 64) {
                const int o = jj + lo2;
                const unsigned long long px2 =
                    *reinterpret_cast<const unsigned long long*>(sxx + o);
                const unsigned long long py2 =
                    *reinterpret_cast<const unsigned long long*>(syy + o);
                const unsigned long long pz2 =
                    *reinterpret_cast<const unsigned long long*>(szz + o);
                const unsigned long long pw2 =
                    *reinterpret_cast<const unsigned long long*>(sww + o);

                const unsigned long long dotA =
                    f2fma(czA2, pz2, f2fma(cyA2, py2, f2mul(cxA2, px2)));
                const unsigned long long dotB =
                    f2fma(czB2, pz2, f2fma(cyB2, py2, f2mul(cxB2, px2)));
                const unsigned long long d2A = f2add(f2fma(n2, dotA, csA2), pw2);
                const unsigned long long d2B = f2add(f2fma(n2, dotB, csB2), pw2);
                float dAa, dAb, dBa, dBb;
                f2unpack(dAa, dAb, d2A);
                f2unpack(dBa, dBb, d2B);

                const bool hit = (dAa <= thA_d) | (dAb <= thA_d) |
                                 (dBa <= thB_d) | (dBb <= thB_d);
                if (__ballot_sync(FULLM, hit)) {           // rare slow path
                    const int base = c0 + jj;
                    unsigned mk;
                    mk = __ballot_sync(FULLM, dAa <= thA_d);
                    while (mk) {
                        const int src = __ffs(mk) - 1; mk &= mk - 1;
                        try_insert(__shfl_sync(FULLM, dAa, src),
                                   base + 2 * src, 0, thA_d, thA_i);
                    }
                    mk = __ballot_sync(FULLM, dAb <= thA_d);
                    while (mk) {
                        const int src = __ffs(mk) - 1; mk &= mk - 1;
                        try_insert(__shfl_sync(FULLM, dAb, src),
                                   base + 2 * src + 1, 0, thA_d, thA_i);
                    }
                    mk = __ballot_sync(FULLM, dBa <= thB_d);
                    while (mk) {
                        const int src = __ffs(mk) - 1; mk &= mk - 1;
                        try_insert(__shfl_sync(FULLM, dBa, src),
                                   base + 2 * src, 1, thB_d, thB_i);
                    }
                    mk = __ballot_sync(FULLM, dBb <= thB_d);
                    while (mk) {
                        const int src = __ffs(mk) - 1; mk &= mk - 1;
                        try_insert(__shfl_sync(FULLM, dBb, src),
                                   base + 2 * src + 1, 1, thB_d, thB_i);
                    }
                }
            }
        }

        // lanes 0..15 -> centroid m0, lanes 16..31 -> centroid m0+1
        {
            const int mm = m0 + (lane >> 4);
            const int kk = lane & 15;
            const int i  = bi;
            float* og = out_grp + ((size_t)((size_t)b * MS + mm) * KNN + kk) * 3;
            og[0] = pb[3 * i + 0];
            og[1] = pb[3 * i + 1];
            og[2] = pb[3 * i + 2];
        }
    }
}

// ---------------------------------------------------------------------------
// kernel_launch: d_in = [x (unused), pos, batch]; out = [centroids | groups].
// Graph-capturable: init kernel + fused persistent kernel, no allocs/syncs.
// ---------------------------------------------------------------------------
extern "C" void kernel_launch(void* const* d_in, const int* in_sizes, int n_in,
                              void* d_out, int out_size) {
    (void)in_sizes; (void)n_in; (void)out_size;
    const float* pos = (const float*)d_in[1];
    float* out      = (float*)d_out;
    float* out_cent = out;                              // B*M*3   = 49152
    float* out_grp  = out + (size_t)NBAT * MS * 3;      // B*M*K*3 = 786432

    // 132KB dynamic smem: > 228/2 KB  =>  1 CTA/SM, so FPS CTAs never share
    // an SM with a worker and all 148 CTAs are co-resident.
    const size_t dsm = 132u * 1024u;
    cudaFuncSetAttribute(fused_kernel, cudaFuncAttributeMaxDynamicSharedMemorySize,
                         (int)dsm);

    init_kernel<<<1, 32>>>();
    fused_kernel<<<NWORK, 1024, dsm>>>(pos, out_cent, out_grp);
}

// round 16
// speedup vs baseline: 1.2203x; 1.0024x over previous
#include <cuda_runtime.h>
#include <float.h>

#define NB   8192
#define NBAT 16
#define MS   1024
#define KNN  16
#define PPT  8        // FPS points per thread (8192 / 1024)
#define NPR  (PPT/2)  // packed pairs per thread
#define CH   2048     // KNN shared-memory chunk (points)
#define GRP  64       // centroids per work item
#define NITEM (NBAT * (MS / GRP))   // 256 work items
#define NWORK 148     // total CTAs (16 FPS + 132 pure workers)
#define FULLM 0xFFFFFFFFu

// ---- work queue / progress (device globals — no allocation) ---------------
__device__ int g_queue;
__device__ int g_progress[NBAT];

// ---- f32x2 helpers: two independent rn fp32 ops per instruction -----------
__device__ __forceinline__ unsigned long long f2pack(float lo, float hi) {
    unsigned long long d;
    asm("mov.b64 %0, {%1, %2};" : "=l"(d)
        : "r"(__float_as_uint(lo)), "r"(__float_as_uint(hi)));
    return d;
}
__device__ __forceinline__ void f2unpack(float& lo, float& hi, unsigned long long s) {
    unsigned a, b;
    asm("mov.b64 {%0, %1}, %2;" : "=r"(a), "=r"(b) : "l"(s));
    lo = __uint_as_float(a); hi = __uint_as_float(b);
}
__device__ __forceinline__ unsigned long long f2add(unsigned long long a,
                                                    unsigned long long b) {
    unsigned long long d;
    asm("add.rn.f32x2 %0, %1, %2;" : "=l"(d) : "l"(a), "l"(b));
    return d;
}
__device__ __forceinline__ unsigned long long f2mul(unsigned long long a,
                                                    unsigned long long b) {
    unsigned long long d;
    asm("mul.rn.f32x2 %0, %1, %2;" : "=l"(d) : "l"(a), "l"(b));
    return d;
}
__device__ __forceinline__ unsigned long long f2fma(unsigned long long a,
                                                    unsigned long long b,
                                                    unsigned long long c) {
    unsigned long long d;
    asm("fma.rn.f32x2 %0, %1, %2, %3;" : "=l"(d) : "l"(a), "l"(b), "l"(c));
    return d;
}

// ---------------------------------------------------------------------------
// init kernel: reset queue + per-batch progress (graph edge orders stores).
// ---------------------------------------------------------------------------
__global__ void init_kernel() {
    if (threadIdx.x == 0) g_queue = 0;
    if (threadIdx.x < NBAT) g_progress[threadIdx.x] = 0;
}

// ---------------------------------------------------------------------------
// FPS body (noinline: isolates codegen of the serial hot loop from the KNN
// worker code). Numerics byte-identical to the verified round-10/15 path.
// ---------------------------------------------------------------------------
static __device__ __noinline__ void fps_body(const float* __restrict__ pos,
                                             float* out_cent, int b) {
    extern __shared__ float sh[];
    __shared__ unsigned shw[32];
    __shared__ int shidx2[2];
    float* shx = sh;
    float* shy = sh + NB;
    float* shz = sh + 2 * NB;

    const int tid  = threadIdx.x;
    const int lane = tid & 31;
    const int w    = tid >> 5;
    const float* pb = pos + (size_t)b * NB * 3;

    for (int i = tid; i < NB; i += 1024) {
        shx[i] = pb[3 * i + 0];
        shy[i] = pb[3 * i + 1];
        shz[i] = pb[3 * i + 2];
    }
    if (tid == 0) { shidx2[0] = 0x7FFFFFFF; shidx2[1] = 0x7FFFFFFF; }
    __syncthreads();

    // pair p holds global indices tid + 2p*1024 (lo) and tid + (2p+1)*1024 (hi)
    unsigned long long rx2[NPR], ry2[NPR], rz2[NPR];
    float md[PPT];
#pragma unroll
    for (int p = 0; p < NPR; p++) {
        int i0 = tid + ((2 * p) << 10);
        int i1 = i0 + 1024;
        rx2[p] = f2pack(shx[i0], shx[i1]);
        ry2[p] = f2pack(shy[i0], shy[i1]);
        rz2[p] = f2pack(shz[i0], shz[i1]);
        md[2 * p] = FLT_MAX; md[2 * p + 1] = FLT_MAX;
    }

    int cur = 0;
    for (int s = 0;; s++) {
        float qx = shx[cur], qy = shy[cur], qz = shz[cur];
        if (tid == 0) {
            float* oc = out_cent + ((size_t)b * MS + s) * 3;
            oc[0] = qx; oc[1] = qy; oc[2] = qz;
            if (((s + 1) & (GRP - 1)) == 0) {        // release 64-group
                __threadfence();                     // order prior stores
                atomicExch(&g_progress[b], s + 1);   // L2-visible publish
            }
        }
        if (s == MS - 1) break;

        unsigned long long nqx = f2pack(-qx, -qx);
        unsigned long long nqy = f2pack(-qy, -qy);
        unsigned long long nqz = f2pack(-qz, -qz);

#pragma unroll
        for (int p = 0; p < NPR; p++) {
            unsigned long long dx = f2add(rx2[p], nqx);
            unsigned long long dy = f2add(ry2[p], nqy);
            unsigned long long dz = f2add(rz2[p], nqz);
            unsigned long long sx = f2mul(dx, dx);
            unsigned long long sy = f2mul(dy, dy);
            unsigned long long sz = f2mul(dz, dz);
            unsigned long long d2 = f2add(f2add(sx, sy), sz);  // ((x²+y²)+z²)
            float a, c;
            f2unpack(a, c, d2);
            md[2 * p]     = fminf(md[2 * p],     a);
            md[2 * p + 1] = fminf(md[2 * p + 1], c);
        }

        float t01 = fmaxf(md[0], md[1]), t23 = fmaxf(md[2], md[3]);
        float t45 = fmaxf(md[4], md[5]), t67 = fmaxf(md[6], md[7]);
        float tmax = fmaxf(fmaxf(t01, t23), fmaxf(t45, t67));

        // non-negative floats: bit pattern is order-preserving as u32
        const unsigned tb = __float_as_uint(tmax);
        const unsigned wv = __reduce_max_sync(FULLM, tb);
        if (lane == 0) shw[w] = wv;
        __syncthreads();                                   // barrier 1
        const unsigned g = __reduce_max_sync(FULLM, shw[lane]);
        if (tid == 0) shidx2[(s + 1) & 1] = 0x7FFFFFFF;
        if (tb == g) {                                     // rare path
            const float gf = __uint_as_float(g);
            int k = 0;
#pragma unroll
            for (int kk = PPT - 1; kk >= 0; kk--)  // descending -> lowest k wins
                if (md[kk] == gf) k = kk;
            atomicMin(&shidx2[s & 1], tid + (k << 10));
        }
        __syncthreads();                                   // barrier 2
        cur = shidx2[s & 1];
    }
}

// ---------------------------------------------------------------------------
// KNN worker body (noinline). Items are gg-major: item = gg*NBAT + b, so the
// claim order tracks availability order (all batches' group 0 first, ...).
// 2 centroids per warp, lists in lanes 0..15 / 16..31 sorted by lex (d2,idx).
// Numerics byte-identical to the verified round-10/15 path.
// ---------------------------------------------------------------------------
static __device__ __noinline__ void knn_body(const float* __restrict__ pos,
                                             const float* out_cent,
                                             float* out_grp) {
    extern __shared__ float sh[];
    __shared__ int s_item;
    float* sxx = sh;
    float* syy = sh + CH;
    float* szz = sh + 2 * CH;
    float* sww = sh + 3 * CH;

    const int tid  = threadIdx.x;
    const int lane = tid & 31;
    const int wid  = tid >> 5;            // 0..31

    for (;;) {
        __syncthreads();                  // protect s_item + smem reuse
        if (tid == 0) s_item = atomicAdd(&g_queue, 1);
        __syncthreads();
        const int item = s_item;
        if (item >= NITEM) break;
        const int gg = item >> 4;         // gg-major claim order
        const int b  = item & 15;
        const int need = (gg + 1) * GRP;

        if (tid == 0) {
            while (atomicAdd(&g_progress[b], 0) < need)    // L2-coherent poll
                __nanosleep(1024);
            __threadfence();                               // acquire
        }
        __syncthreads();

        const int m0 = (gg << 6) + wid * 2;     // centroid pair for this warp
        const float* cpA = out_cent + ((size_t)b * MS + m0) * 3;
        const float cxA = cpA[0], cyA = cpA[1], czA = cpA[2];
        const float cxB = cpA[3], cyB = cpA[4], czB = cpA[5];
        const float csA = __fadd_rn(__fadd_rn(__fmul_rn(cxA, cxA),
                                              __fmul_rn(cyA, cyA)),
                                    __fmul_rn(czA, czA));
        const float csB = __fadd_rn(__fadd_rn(__fmul_rn(cxB, cxB),
                                              __fmul_rn(cyB, cyB)),
                                    __fmul_rn(czB, czB));
        const unsigned long long cxA2 = f2pack(cxA, cxA), cxB2 = f2pack(cxB, cxB);
        const unsigned long long cyA2 = f2pack(cyA, cyA), cyB2 = f2pack(cyB, cyB);
        const unsigned long long czA2 = f2pack(czA, czA), czB2 = f2pack(czB, czB);
        const unsigned long long csA2 = f2pack(csA, csA), csB2 = f2pack(csB, csB);
        const unsigned long long n2   = f2pack(-2.0f, -2.0f);
        const float* pb = pos + (size_t)b * NB * 3;

        float bd = FLT_MAX;
        int   bi = 0x7FFFFFFF;
        float thA_d = FLT_MAX, thB_d = FLT_MAX;
        int   thA_i = 0x7FFFFFFF, thB_i = 0x7FFFFFFF;

        auto try_insert = [&](float cd, int ci, int half, float& th_d, int& th_i) {
            if ((cd < th_d) || (cd == th_d && ci < th_i)) {
                const bool less = (bd < cd) || (bd == cd && bi < ci);
                const unsigned lm =
                    (__ballot_sync(FULLM, less) >> (half << 4)) & 0xFFFFu;
                const int pp = (half << 4) + __popc(lm);
                const float ud = __shfl_up_sync(FULLM, bd, 1);
                const int   ui = __shfl_up_sync(FULLM, bi, 1);
                if ((lane >> 4) == half) {
                    if (lane == pp)      { bd = cd; bi = ci; }
                    else if (lane > pp)  { bd = ud; bi = ui; }
                }
                th_d = __shfl_sync(FULLM, bd, (half << 4) + 15);
                th_i = __shfl_sync(FULLM, bi, (half << 4) + 15);
            }
        };

        const int lo2 = 2 * lane;

        for (int c0 = 0; c0 < NB; c0 += CH) {
            __syncthreads();
            for (int j = tid; j < CH; j += 1024) {
                float px = pb[3 * (c0 + j) + 0];
                float py = pb[3 * (c0 + j) + 1];
                float pz = pb[3 * (c0 + j) + 2];
                float ps = __fadd_rn(__fadd_rn(__fmul_rn(px, px),
                                               __fmul_rn(py, py)),
                                     __fmul_rn(pz, pz));
                sxx[j] = px; syy[j] = py; szz[j] = pz; sww[j] = ps;
            }
            __syncthreads();

#pragma unroll 4
            for (int jj = 0; jj < CH; jj += 64) {
                const int o = jj + lo2;
                const unsigned long long px2 =
                    *reinterpret_cast<const unsigned long long*>(sxx + o);
                const unsigned long long py2 =
                    *reinterpret_cast<const unsigned long long*>(syy + o);
                const unsigned long long pz2 =
                    *reinterpret_cast<const unsigned long long*>(szz + o);
                const unsigned long long pw2 =
                    *reinterpret_cast<const unsigned long long*>(sww + o);

                const unsigned long long dotA =
                    f2fma(czA2, pz2, f2fma(cyA2, py2, f2mul(cxA2, px2)));
                const unsigned long long dotB =
                    f2fma(czB2, pz2, f2fma(cyB2, py2, f2mul(cxB2, px2)));
                const unsigned long long d2A = f2add(f2fma(n2, dotA, csA2), pw2);
                const unsigned long long d2B = f2add(f2fma(n2, dotB, csB2), pw2);
                float dAa, dAb, dBa, dBb;
                f2unpack(dAa, dAb, d2A);
                f2unpack(dBa, dBb, d2B);

                const bool hit = (dAa <= thA_d) | (dAb <= thA_d) |
                                 (dBa <= thB_d) | (dBb <= thB_d);
                if (__ballot_sync(FULLM, hit)) {           // rare slow path
                    const int base = c0 + jj;
                    unsigned mk;
                    mk = __ballot_sync(FULLM, dAa <= thA_d);
                    while (mk) {
                        const int src = __ffs(mk) - 1; mk &= mk - 1;
                        try_insert(__shfl_sync(FULLM, dAa, src),
                                   base + 2 * src, 0, thA_d, thA_i);
                    }
                    mk = __ballot_sync(FULLM, dAb <= thA_d);
                    while (mk) {
                        const int src = __ffs(mk) - 1; mk &= mk - 1;
                        try_insert(__shfl_sync(FULLM, dAb, src),
                                   base + 2 * src + 1, 0, thA_d, thA_i);
                    }
                    mk = __ballot_sync(FULLM, dBa <= thB_d);
                    while (mk) {
                        const int src = __ffs(mk) - 1; mk &= mk - 1;
                        try_insert(__shfl_sync(FULLM, dBa, src),
                                   base + 2 * src, 1, thB_d, thB_i);
                    }
                    mk = __ballot_sync(FULLM, dBb <= thB_d);
                    while (mk) {
                        const int src = __ffs(mk) - 1; mk &= mk - 1;
                        try_insert(__shfl_sync(FULLM, dBb, src),
                                   base + 2 * src + 1, 1, thB_d, thB_i);
                    }
                }
            }
        }

        // lanes 0..15 -> centroid m0, lanes 16..31 -> centroid m0+1
        {
            const int mm = m0 + (lane >> 4);
            const int kk = lane & 15;
            const int i  = bi;
            float* og = out_grp + ((size_t)((size_t)b * MS + mm) * KNN + kk) * 3;
            og[0] = pb[3 * i + 0];
            og[1] = pb[3 * i + 1];
            og[2] = pb[3 * i + 2];
        }
    }
}

// ---------------------------------------------------------------------------
// Fused persistent kernel: CTAs 0..15 run FPS then join the worker pool;
// CTAs 16..147 are pure KNN workers. 132KB dynamic smem -> 1 CTA/SM, all
// 148 CTAs co-resident; termination is scheduling-independent regardless
// (FPS CTAs never wait, progress is monotone).
// ---------------------------------------------------------------------------
__global__ __launch_bounds__(1024, 1)
void fused_kernel(const float* __restrict__ pos, float* out_cent,
                  float* out_grp) {
    if (blockIdx.x < NBAT)
        fps_body(pos, out_cent, blockIdx.x);
    knn_body(pos, out_cent, out_grp);
}

// ---------------------------------------------------------------------------
// kernel_launch: d_in = [x (unused), pos, batch]; out = [centroids | groups].
// Graph-capturable: init kernel + fused persistent kernel, no allocs/syncs.
// ---------------------------------------------------------------------------
extern "C" void kernel_launch(void* const* d_in, const int* in_sizes, int n_in,
                              void* d_out, int out_size) {
    (void)in_sizes; (void)n_in; (void)out_size;
    const float* pos = (const float*)d_in[1];
    float* out      = (float*)d_out;
    float* out_cent = out;                              // B*M*3   = 49152
    float* out_grp  = out + (size_t)NBAT * MS * 3;      // B*M*K*3 = 786432

    const size_t dsm = 132u * 1024u;   // 1 CTA/SM, covers 96KB FPS / 32KB KNN
    cudaFuncSetAttribute(fused_kernel, cudaFuncAttributeMaxDynamicSharedMemorySize,
                         (int)dsm);

    init_kernel<<<1, 32>>>();
    fused_kernel<<<NWORK, 1024, dsm>>>(pos, out_cent, out_grp);
}